// round 6
// baseline (speedup 1.0000x reference)
#include <cuda_runtime.h>
#include <cuda_bf16.h>
#include <cstdint>
#include <cmath>

// ============================================================================
// ProtoNetLayer — legacy tensor-core path (mma.sync bf16, sm_103-family safe).
// The harness's ptxas target is sm_103 (family), which rejects all tcgen05/
// TMEM PTX ("not supported on .target sm_103"), so we use the family-agnostic
// set: cp.async + ldmatrix + mma.sync.m16n8k16.bf16.
//
//   scores[n,c] = -sqrt(max(1 + |P_c|^2 - 2 * z_n . P_c, 0))
//   Y = X @ proj - (mean @ proj)    [kernel1, K=1024, fused row-normalize]
//   z = Y / max(|Y|, eps)  -> bf16 scratch
//   S = z @ P^T                     [kernel2, K=256, fused sqrt epilogue]
//
// R6 fix: proto_gemm2's A stage buffer is 128 rows x 128B = 16384 B, not 8192.
// The old 8192 stride made stage-1 A clobber B buffer 0 mid-mma (the observed
// ~2% rel_err). Buffers resized: sA 2x16384, sB at +32768, SMEM2 = 99328.
// ============================================================================

#define N_ROWS  32768
#define D_IN    1024
#define D_PROJ  256
#define N_CLS   256
#define TM      128
#define KT      64

#define SMEM1   101376   // A(2x16K) + B(2x32K) + c(1K) + red(2K)
#define SMEM2   99328    // A(2x16K) + B(2x32K) + p2(1K)

// device-global scratch (no runtime allocation allowed)
__device__ __align__(256) __nv_bfloat16 g_Bw[D_PROJ * D_IN];           // projT bf16 [256][1024]
__device__ __align__(256) __nv_bfloat16 g_Bp[N_CLS * D_PROJ];          // prototypes bf16 [256][256]
__device__ __align__(256) __nv_bfloat16 g_Z[(size_t)N_ROWS * D_PROJ];  // normalized Z bf16 (16MB)
__device__ float g_c[D_PROJ];                                          // mean @ proj
__device__ float g_p2[N_CLS];                                          // |P_c|^2

// ---------------------------------------------------------------------------
// asm helpers (all family-agnostic: sm_75/sm_80 features)
// ---------------------------------------------------------------------------
__device__ __forceinline__ uint32_t smem_u32(const void* p) {
    uint32_t a;
    asm("{ .reg .u64 t; cvta.to.shared.u64 t, %1; cvt.u32.u64 %0, t; }" : "=r"(a) : "l"(p));
    return a;
}
__device__ __forceinline__ void ldmx4(uint32_t* r, uint32_t a) {
    asm volatile("ldmatrix.sync.aligned.m8n8.x4.shared.b16 {%0,%1,%2,%3}, [%4];"
                 : "=r"(r[0]), "=r"(r[1]), "=r"(r[2]), "=r"(r[3]) : "r"(a));
}
__device__ __forceinline__ void mmabf16(float* c, const uint32_t* a, uint32_t b0, uint32_t b1) {
    asm volatile("mma.sync.aligned.m16n8k16.row.col.f32.bf16.bf16.f32 "
                 "{%0,%1,%2,%3}, {%4,%5,%6,%7}, {%8,%9}, {%0,%1,%2,%3};"
                 : "+f"(c[0]), "+f"(c[1]), "+f"(c[2]), "+f"(c[3])
                 : "r"(a[0]), "r"(a[1]), "r"(a[2]), "r"(a[3]), "r"(b0), "r"(b1));
}
__device__ __forceinline__ void cp16(uint32_t d, const void* s) {
    asm volatile("cp.async.cg.shared.global [%0], [%1], 16;" :: "r"(d), "l"(s) : "memory");
}
#define CP_COMMIT() asm volatile("cp.async.commit_group;" ::: "memory")
#define CP_WAIT0()  asm volatile("cp.async.wait_group 0;" ::: "memory")

// shared 64x64 warp-tile mma over one K=64 stage (SW128-swizzled smem, 128B rows)
__device__ __forceinline__ void mma_stage(uint32_t Abase, uint32_t Bbase,
                                          int lane, int wm, int wn,
                                          float (&acc)[4][8][4]) {
    const int ra  = (lane & 7) + ((lane >> 3) & 1) * 8;   // A: lanes 0-15 rows 0-15
    const int kxa = ((lane >> 4) & 1) * 16;               //    lanes 16-31 -> k+8 (16B)
    const int rb  = (lane & 7) + ((lane >> 4) & 1) * 8;   // B: lanes 16-31 rows +8
    const int kxb = ((lane >> 3) & 1) * 16;               //    lanes 8-15,24-31 -> k+8
    const int xa = (lane & 7) << 4;                       // swizzle xor (row&7)<<4
    const uint32_t Aw = Abase + (uint32_t)(wm * 64 + ra) * 128;
    const uint32_t Bw = Bbase + (uint32_t)(wn * 64 + rb) * 128;
    #pragma unroll
    for (int k16 = 0; k16 < 4; k16++) {
        uint32_t aF[4][4], bF[4][4];
        #pragma unroll
        for (int mi = 0; mi < 4; mi++)
            ldmx4(aF[mi], Aw + mi * 16 * 128 + (uint32_t)((k16 * 32 + kxa) ^ xa));
        #pragma unroll
        for (int nj = 0; nj < 4; nj++)
            ldmx4(bF[nj], Bw + nj * 16 * 128 + (uint32_t)((k16 * 32 + kxb) ^ xa));
        #pragma unroll
        for (int mi = 0; mi < 4; mi++)
            #pragma unroll
            for (int nj = 0; nj < 4; nj++) {
                mmabf16(acc[mi][2 * nj],     aF[mi], bF[nj][0], bF[nj][1]);
                mmabf16(acc[mi][2 * nj + 1], aF[mi], bF[nj][2], bF[nj][3]);
            }
    }
}

// ---------------------------------------------------------------------------
// Prep: projT->bf16, prototypes->bf16, c = mean@proj, p2 = |P|^2 rowwise
// grid = 1024 + 256 + 2 blocks x 256 threads
// ---------------------------------------------------------------------------
__global__ void proto_prep(const float* __restrict__ mean,
                           const float* __restrict__ proj,
                           const float* __restrict__ proto) {
    int b = blockIdx.x, t = threadIdx.x;
    if (b < D_IN) {
        g_Bw[(size_t)t * D_IN + b] = __float2bfloat16(proj[(size_t)b * D_PROJ + t]);
    } else if (b < D_IN + N_CLS) {
        int r = b - D_IN;
        g_Bp[r * D_PROJ + t] = __float2bfloat16(proto[r * D_PROJ + t]);
    } else if (b == D_IN + N_CLS) {
        float acc = 0.f;
        for (int d = 0; d < D_IN; d++) acc = fmaf(mean[d], proj[(size_t)d * D_PROJ + t], acc);
        g_c[t] = acc;
    } else {
        float acc = 0.f;
        const float* p = proto + (size_t)t * D_PROJ;
        for (int k = 0; k < D_PROJ; k++) acc = fmaf(p[k], p[k], acc);
        g_p2[t] = acc;
    }
}

// ---------------------------------------------------------------------------
// Kernel 1: Y = X@projT^T - c, row-normalize, write Z bf16.
// 256 CTAs x 256 threads, warp grid 2(M) x 4(N), warp tile 64x64, K pipeline.
// ---------------------------------------------------------------------------
__global__ void __launch_bounds__(256, 1) proto_gemm1(const float* __restrict__ X) {
    extern __shared__ __align__(128) unsigned char smem[];
    const uint32_t sb = smem_u32(smem);
    const uint32_t sA = sb;              // 2 x 16384
    const uint32_t sB = sb + 32768;      // 2 x 32768
    float* cs  = (float*)(smem + 98304);
    float* red = (float*)(smem + 99328); // [128][4]
    const int tid = threadIdx.x, lane = tid & 31, wid = tid >> 5;
    const int wm = wid & 1, wn = wid >> 1;
    const int m0 = blockIdx.x * TM;

    cs[tid & 255] = g_c[tid & 255];

    float acc[4][8][4];
    #pragma unroll
    for (int a = 0; a < 4; a++)
        #pragma unroll
        for (int b = 0; b < 8; b++)
            #pragma unroll
            for (int c = 0; c < 4; c++) acc[a][b][c] = 0.f;

    // A (X f32 -> bf16) mapping: 16 float4/row, 16 rows/iter, 8 iters
    const int tx = tid & 15, ty = tid >> 4;
    const float* gA = X + (size_t)(m0 + ty) * D_IN + tx * 4;
    const uint32_t stsAoff = (uint32_t)(ty * 128) + (uint32_t)((tx * 8) ^ ((ty & 7) << 4));
    // B (projT bf16) mapping: 8 x 16B/row, 32 rows/iter, 8 iters
    const int bx = tid & 7, by = tid >> 3;
    const __nv_bfloat16* gB = g_Bw + (size_t)by * D_IN + bx * 8;
    const uint32_t cpBoff = (uint32_t)(by * 128) + (uint32_t)((bx * 16) ^ ((by & 7) << 4));

    float4 aR[8];
    // ---- prologue: stage 0 ----
    #pragma unroll
    for (int i = 0; i < 8; i++) aR[i] = *(const float4*)(gA + (size_t)(16 * i) * D_IN);
    #pragma unroll
    for (int i = 0; i < 8; i++) cp16(sB + cpBoff + i * 32 * 128, gB + (size_t)(32 * i) * D_IN);
    CP_COMMIT();
    #pragma unroll
    for (int i = 0; i < 8; i++) {
        __nv_bfloat162 l2 = __floats2bfloat162_rn(aR[i].x, aR[i].y);
        __nv_bfloat162 h2 = __floats2bfloat162_rn(aR[i].z, aR[i].w);
        *(uint2*)(smem + stsAoff + i * 16 * 128) =
            make_uint2(*(uint32_t*)&l2, *(uint32_t*)&h2);
    }
    CP_WAIT0();
    __syncthreads();

    // ---- main K pipeline: 16 stages of K=64 ----
    for (int kt = 0; kt < D_IN / KT; kt++) {
        const int cur = kt & 1, nxt = cur ^ 1;
        const bool more = (kt + 1) < (D_IN / KT);
        if (more) {
            const int kb = (kt + 1) * KT;
            #pragma unroll
            for (int i = 0; i < 8; i++)
                aR[i] = *(const float4*)(gA + (size_t)(16 * i) * D_IN + kb);
            #pragma unroll
            for (int i = 0; i < 8; i++)
                cp16(sB + nxt * 32768 + cpBoff + i * 32 * 128,
                     gB + (size_t)(32 * i) * D_IN + kb);
            CP_COMMIT();
        }
        mma_stage(sA + cur * 16384, sB + cur * 32768, lane, wm, wn, acc);
        if (more) {
            #pragma unroll
            for (int i = 0; i < 8; i++) {
                __nv_bfloat162 l2 = __floats2bfloat162_rn(aR[i].x, aR[i].y);
                __nv_bfloat162 h2 = __floats2bfloat162_rn(aR[i].z, aR[i].w);
                *(uint2*)(smem + nxt * 16384 + stsAoff + i * 16 * 128) =
                    make_uint2(*(uint32_t*)&l2, *(uint32_t*)&h2);
            }
            CP_WAIT0();
        }
        __syncthreads();
    }

    // ---- epilogue: subtract c, row-norm, normalize, write Z bf16 ----
    const int c0 = wn * 64 + 2 * (lane & 3);
    float s[4][2];
    #pragma unroll
    for (int mi = 0; mi < 4; mi++) { s[mi][0] = 0.f; s[mi][1] = 0.f; }
    #pragma unroll
    for (int mi = 0; mi < 4; mi++)
        #pragma unroll
        for (int ni = 0; ni < 8; ni++)
            #pragma unroll
            for (int j = 0; j < 4; j++) {
                float v = acc[mi][ni][j] - cs[c0 + ni * 8 + (j & 1)];
                acc[mi][ni][j] = v;
                s[mi][j >> 1] = fmaf(v, v, s[mi][j >> 1]);
            }
    #pragma unroll
    for (int mi = 0; mi < 4; mi++)
        #pragma unroll
        for (int h = 0; h < 2; h++) {
            s[mi][h] += __shfl_xor_sync(0xffffffffu, s[mi][h], 1);
            s[mi][h] += __shfl_xor_sync(0xffffffffu, s[mi][h], 2);
        }
    const int r0 = wm * 64 + (lane >> 2);
    if ((lane & 3) == 0) {
        #pragma unroll
        for (int mi = 0; mi < 4; mi++)
            #pragma unroll
            for (int h = 0; h < 2; h++)
                red[(r0 + mi * 16 + h * 8) * 4 + wn] = s[mi][h];
    }
    __syncthreads();
    #pragma unroll
    for (int mi = 0; mi < 4; mi++)
        #pragma unroll
        for (int h = 0; h < 2; h++) {
            const int r = r0 + mi * 16 + h * 8;
            float t = red[r * 4 + 0] + red[r * 4 + 1] + red[r * 4 + 2] + red[r * 4 + 3];
            float inv = 1.f / fmaxf(sqrtf(t), 1e-12f);
            const size_t rowoff = (size_t)(m0 + r) * D_PROJ;
            #pragma unroll
            for (int ni = 0; ni < 8; ni++) {
                __nv_bfloat162 zz = __floats2bfloat162_rn(acc[mi][ni][2 * h] * inv,
                                                          acc[mi][ni][2 * h + 1] * inv);
                *(uint32_t*)&g_Z[rowoff + c0 + ni * 8] = *(uint32_t*)&zz;
            }
        }
}

// ---------------------------------------------------------------------------
// Kernel 2: S = Z @ P^T (K=256), scores = -sqrt(max(1 + p2 - 2 S, 0))
// ---------------------------------------------------------------------------
__global__ void __launch_bounds__(256, 1) proto_gemm2(float* __restrict__ out) {
    extern __shared__ __align__(128) unsigned char smem[];
    const uint32_t sb = smem_u32(smem);
    const uint32_t sA = sb;              // 2 x 16384 (128 rows x 128B per stage)
    const uint32_t sB = sb + 32768;      // 2 x 32768
    float* p2s = (float*)(smem + 98304);
    const int tid = threadIdx.x, lane = tid & 31, wid = tid >> 5;
    const int wm = wid & 1, wn = wid >> 1;
    const int m0 = blockIdx.x * TM;

    p2s[tid & 255] = g_p2[tid & 255];

    float acc[4][8][4];
    #pragma unroll
    for (int a = 0; a < 4; a++)
        #pragma unroll
        for (int b = 0; b < 8; b++)
            #pragma unroll
            for (int c = 0; c < 4; c++) acc[a][b][c] = 0.f;

    const int ax = tid & 7, ay = tid >> 3;  // shared mapping: 8x16B per 128B row
    const __nv_bfloat16* gA = g_Z + (size_t)(m0 + ay) * D_PROJ + ax * 8;
    const __nv_bfloat16* gB = g_Bp + (size_t)ay * D_PROJ + ax * 8;
    const uint32_t off = (uint32_t)(ay * 128) + (uint32_t)((ax * 16) ^ ((ay & 7) << 4));

    // ---- prologue ----
    #pragma unroll
    for (int i = 0; i < 4; i++) cp16(sA + off + i * 32 * 128, gA + (size_t)(32 * i) * D_PROJ);
    #pragma unroll
    for (int i = 0; i < 8; i++) cp16(sB + off + i * 32 * 128, gB + (size_t)(32 * i) * D_PROJ);
    CP_COMMIT();
    CP_WAIT0();
    __syncthreads();

    for (int kt = 0; kt < D_PROJ / KT; kt++) {
        const int cur = kt & 1, nxt = cur ^ 1;
        const bool more = (kt + 1) < (D_PROJ / KT);
        if (more) {
            const int kb = (kt + 1) * KT;
            #pragma unroll
            for (int i = 0; i < 4; i++)
                cp16(sA + nxt * 16384 + off + i * 32 * 128,
                     gA + (size_t)(32 * i) * D_PROJ + kb);
            #pragma unroll
            for (int i = 0; i < 8; i++)
                cp16(sB + nxt * 32768 + off + i * 32 * 128,
                     gB + (size_t)(32 * i) * D_PROJ + kb);
            CP_COMMIT();
        }
        mma_stage(sA + cur * 16384, sB + cur * 32768, lane, wm, wn, acc);
        if (more) CP_WAIT0();
        __syncthreads();
    }

    // ---- epilogue: score = -sqrt(max(1 + p2 - 2 s, 0)) ----
    const int c0 = wn * 64 + 2 * (lane & 3);
    const int r0 = wm * 64 + (lane >> 2);
    #pragma unroll
    for (int mi = 0; mi < 4; mi++)
        #pragma unroll
        for (int h = 0; h < 2; h++) {
            const size_t rowoff = (size_t)(m0 + r0 + mi * 16 + h * 8) * N_CLS;
            #pragma unroll
            for (int ni = 0; ni < 8; ni++) {
                const int cc = c0 + ni * 8;
                float2 v;
                v.x = -sqrtf(fmaxf(1.0f + p2s[cc]     - 2.f * acc[mi][ni][2 * h],     0.f));
                v.y = -sqrtf(fmaxf(1.0f + p2s[cc + 1] - 2.f * acc[mi][ni][2 * h + 1], 0.f));
                *(float2*)(out + rowoff + cc) = v;
            }
        }
}

// ---------------------------------------------------------------------------
// Host launcher (graph-capturable: kernel launches only)
// ---------------------------------------------------------------------------
extern "C" void kernel_launch(void* const* d_in, const int* in_sizes, int n_in,
                              void* d_out, int out_size) {
    const float* X     = (const float*)d_in[0];
    const float* mean  = (const float*)d_in[1];
    const float* proj  = (const float*)d_in[2];
    const float* proto = (const float*)d_in[3];
    float* out = (float*)d_out;

    cudaFuncSetAttribute(proto_gemm1, cudaFuncAttributeMaxDynamicSharedMemorySize, SMEM1);
    cudaFuncSetAttribute(proto_gemm2, cudaFuncAttributeMaxDynamicSharedMemorySize, SMEM2);

    proto_prep<<<D_IN + N_CLS + 2, 256>>>(mean, proj, proto);
    proto_gemm1<<<N_ROWS / TM, 256, SMEM1>>>(X);
    proto_gemm2<<<N_ROWS / TM, 256, SMEM2>>>(out);
}

// round 7
// speedup vs baseline: 1.0487x; 1.0487x over previous
#include <cuda_runtime.h>
#include <cuda_bf16.h>
#include <cstdint>
#include <cmath>

// ============================================================================
// ProtoNetLayer — fused single-pass mma.sync bf16 kernel (sm_103-family safe).
// (tcgen05 unavailable: harness ptxas target is sm_103 family, rejects it.)
//
//   scores[n,c] = -sqrt(max(1 + |P_c|^2 - 2 * z_n . P_c, 0))
//   phase 1: Y = X @ projT^T - c   (K=1024, cp.async/ldmatrix/mma pipeline)
//   norm:    z = Y / max(|Y|,eps)  -> bf16 in SHARED MEMORY (64 KB, no gmem)
//   phase 2: S = z @ P^T (K=256, A from smem Z panels) + sqrt epilogue
//
// R7: prep rewritten (42.5us -> ~4us: tiled transpose, unrolled reductions),
//     gemm2 fused into gemm1 via smem-resident Z (kills 32MB roundtrip +
//     second kernel's prologue/tail).
// ============================================================================

#define N_ROWS  32768
#define D_IN    1024
#define D_PROJ  256
#define N_CLS   256
#define TM      128
#define KT      64

// fused-kernel smem layout (bytes)
#define OFF_A    0        // phase1 A stages: 2 x 16384
#define OFF_B    32768    // B stages (projT then prototypes): 2 x 32768
#define OFF_C    98304    // c[256] f32
#define OFF_RED  99328    // red[128][4] f32
#define OFF_P2   101376   // p2[256] f32
#define OFF_Z    102400   // Z panels: 4 x 16384 (128 rows x 128B, swizzled)
#define SMEMF    167936

// device-global scratch (no runtime allocation allowed)
__device__ __align__(256) __nv_bfloat16 g_Bw[D_PROJ * D_IN];   // projT bf16 [256][1024]
__device__ __align__(256) __nv_bfloat16 g_Bp[N_CLS * D_PROJ];  // prototypes bf16 [256][256]
__device__ float g_c[D_PROJ];                                  // mean @ proj
__device__ float g_p2[N_CLS];                                  // |P_c|^2

// ---------------------------------------------------------------------------
// asm helpers (family-agnostic: sm_75/sm_80 features)
// ---------------------------------------------------------------------------
__device__ __forceinline__ uint32_t smem_u32(const void* p) {
    uint32_t a;
    asm("{ .reg .u64 t; cvta.to.shared.u64 t, %1; cvt.u32.u64 %0, t; }" : "=r"(a) : "l"(p));
    return a;
}
__device__ __forceinline__ void ldmx4(uint32_t* r, uint32_t a) {
    asm volatile("ldmatrix.sync.aligned.m8n8.x4.shared.b16 {%0,%1,%2,%3}, [%4];"
                 : "=r"(r[0]), "=r"(r[1]), "=r"(r[2]), "=r"(r[3]) : "r"(a));
}
__device__ __forceinline__ void mmabf16(float* c, const uint32_t* a, uint32_t b0, uint32_t b1) {
    asm volatile("mma.sync.aligned.m16n8k16.row.col.f32.bf16.bf16.f32 "
                 "{%0,%1,%2,%3}, {%4,%5,%6,%7}, {%8,%9}, {%0,%1,%2,%3};"
                 : "+f"(c[0]), "+f"(c[1]), "+f"(c[2]), "+f"(c[3])
                 : "r"(a[0]), "r"(a[1]), "r"(a[2]), "r"(a[3]), "r"(b0), "r"(b1));
}
__device__ __forceinline__ void cp16(uint32_t d, const void* s) {
    asm volatile("cp.async.cg.shared.global [%0], [%1], 16;" :: "r"(d), "l"(s) : "memory");
}
#define CP_COMMIT() asm volatile("cp.async.commit_group;" ::: "memory")
#define CP_WAIT0()  asm volatile("cp.async.wait_group 0;" ::: "memory")

// shared 64x64 warp-tile mma over one K=64 stage (swizzled smem, 128B rows)
__device__ __forceinline__ void mma_stage(uint32_t Abase, uint32_t Bbase,
                                          int lane, int wm, int wn,
                                          float (&acc)[4][8][4]) {
    const int ra  = (lane & 7) + ((lane >> 3) & 1) * 8;
    const int kxa = ((lane >> 4) & 1) * 16;
    const int rb  = (lane & 7) + ((lane >> 4) & 1) * 8;
    const int kxb = ((lane >> 3) & 1) * 16;
    const int xa = (lane & 7) << 4;
    const uint32_t Aw = Abase + (uint32_t)(wm * 64 + ra) * 128;
    const uint32_t Bw = Bbase + (uint32_t)(wn * 64 + rb) * 128;
    #pragma unroll
    for (int k16 = 0; k16 < 4; k16++) {
        uint32_t aF[4][4], bF[4][4];
        #pragma unroll
        for (int mi = 0; mi < 4; mi++)
            ldmx4(aF[mi], Aw + mi * 16 * 128 + (uint32_t)((k16 * 32 + kxa) ^ xa));
        #pragma unroll
        for (int nj = 0; nj < 4; nj++)
            ldmx4(bF[nj], Bw + nj * 16 * 128 + (uint32_t)((k16 * 32 + kxb) ^ xa));
        #pragma unroll
        for (int mi = 0; mi < 4; mi++)
            #pragma unroll
            for (int nj = 0; nj < 4; nj++) {
                mmabf16(acc[mi][2 * nj],     aF[mi], bF[nj][0], bF[nj][1]);
                mmabf16(acc[mi][2 * nj + 1], aF[mi], bF[nj][2], bF[nj][3]);
            }
    }
}

// ---------------------------------------------------------------------------
// Prep (42 blocks x 256 threads, all parts parallel):
//  blocks 0..31 : projT transpose via smem tile (coalesced both directions)
//  block  32    : c = mean @ proj (coalesced rows, 4 accumulators)
//  block  33    : p2 = rowwise |P|^2
//  blocks 34..41: prototypes f32 -> bf16 (vectorized elementwise)
// ---------------------------------------------------------------------------
__global__ void proto_prep(const float* __restrict__ mean,
                           const float* __restrict__ proj,
                           const float* __restrict__ proto) {
    const int b = blockIdx.x, t = threadIdx.x;
    if (b < 32) {
        __shared__ __nv_bfloat16 tile[32][258];   // +2 pad: kill bank conflicts
        const int r0 = b * 32;
        const int r = t >> 3, cq = (t & 7) * 32;  // 8 threads per row, 32 cols each
        #pragma unroll
        for (int j = 0; j < 8; j++) {
            float4 v = *(const float4*)(proj + (size_t)(r0 + r) * D_PROJ + cq + 4 * j);
            tile[r][cq + 4 * j + 0] = __float2bfloat16(v.x);
            tile[r][cq + 4 * j + 1] = __float2bfloat16(v.y);
            tile[r][cq + 4 * j + 2] = __float2bfloat16(v.z);
            tile[r][cq + 4 * j + 3] = __float2bfloat16(v.w);
        }
        __syncthreads();
        // thread t owns output column c = t: write 32 consecutive k's (64B)
        #pragma unroll
        for (int i = 0; i < 4; i++) {
            uint32_t w[4];
            #pragma unroll
            for (int j = 0; j < 4; j++) {
                __nv_bfloat162 p2v;
                p2v.x = tile[i * 8 + 2 * j][t];
                p2v.y = tile[i * 8 + 2 * j + 1][t];
                w[j] = *(uint32_t*)&p2v;
            }
            *(uint4*)&g_Bw[(size_t)t * D_IN + r0 + i * 8] =
                make_uint4(w[0], w[1], w[2], w[3]);
        }
    } else if (b == 32) {
        float a0 = 0.f, a1 = 0.f, a2 = 0.f, a3 = 0.f;
        for (int d = 0; d < D_IN; d += 4) {
            a0 = fmaf(mean[d],     proj[(size_t)d       * D_PROJ + t], a0);
            a1 = fmaf(mean[d + 1], proj[(size_t)(d + 1) * D_PROJ + t], a1);
            a2 = fmaf(mean[d + 2], proj[(size_t)(d + 2) * D_PROJ + t], a2);
            a3 = fmaf(mean[d + 3], proj[(size_t)(d + 3) * D_PROJ + t], a3);
        }
        g_c[t] = (a0 + a1) + (a2 + a3);
    } else if (b == 33) {
        float a0 = 0.f, a1 = 0.f;
        const float* p = proto + (size_t)t * D_PROJ;
        #pragma unroll 4
        for (int k = 0; k < D_PROJ; k += 8) {
            float4 u = *(const float4*)(p + k);
            float4 v = *(const float4*)(p + k + 4);
            a0 = fmaf(u.x, u.x, fmaf(u.y, u.y, fmaf(u.z, u.z, fmaf(u.w, u.w, a0))));
            a1 = fmaf(v.x, v.x, fmaf(v.y, v.y, fmaf(v.z, v.z, fmaf(v.w, v.w, a1))));
        }
        g_p2[t] = a0 + a1;
    } else {
        const int base = (b - 34) * 8192 + t * 32;
        #pragma unroll
        for (int i = 0; i < 4; i++) {
            float4 u = *(const float4*)(proto + base + 8 * i);
            float4 v = *(const float4*)(proto + base + 8 * i + 4);
            __nv_bfloat162 w0 = __floats2bfloat162_rn(u.x, u.y);
            __nv_bfloat162 w1 = __floats2bfloat162_rn(u.z, u.w);
            __nv_bfloat162 w2 = __floats2bfloat162_rn(v.x, v.y);
            __nv_bfloat162 w3 = __floats2bfloat162_rn(v.z, v.w);
            *(uint4*)&g_Bp[base + 8 * i] = make_uint4(
                *(uint32_t*)&w0, *(uint32_t*)&w1, *(uint32_t*)&w2, *(uint32_t*)&w3);
        }
    }
}

// ---------------------------------------------------------------------------
// Fused kernel: 256 CTAs x 256 threads, warp grid 2(M) x 4(N), tile 64x64.
// ---------------------------------------------------------------------------
__global__ void __launch_bounds__(256, 1) proto_fused(const float* __restrict__ X,
                                                      float* __restrict__ out) {
    extern __shared__ __align__(128) unsigned char smem[];
    const uint32_t sb = smem_u32(smem);
    const uint32_t sA = sb + OFF_A;
    const uint32_t sB = sb + OFF_B;
    const uint32_t sZ = sb + OFF_Z;
    float* cs  = (float*)(smem + OFF_C);
    float* red = (float*)(smem + OFF_RED);
    float* p2s = (float*)(smem + OFF_P2);
    const int tid = threadIdx.x, lane = tid & 31, wid = tid >> 5;
    const int wm = wid & 1, wn = wid >> 1;
    const int m0 = blockIdx.x * TM;

    cs[tid]  = g_c[tid];
    p2s[tid] = g_p2[tid];

    float acc[4][8][4];
    #pragma unroll
    for (int a = 0; a < 4; a++)
        #pragma unroll
        for (int b = 0; b < 8; b++)
            #pragma unroll
            for (int c = 0; c < 4; c++) acc[a][b][c] = 0.f;

    // A (X f32 -> bf16): 16 float4/row, 16 rows/iter, 8 iters
    const int tx = tid & 15, ty = tid >> 4;
    const float* gA = X + (size_t)(m0 + ty) * D_IN + tx * 4;
    const uint32_t stsAoff = (uint32_t)(ty * 128) + (uint32_t)((tx * 8) ^ ((ty & 7) << 4));
    // B streams (projT then prototypes): 8 x 16B/row, 32 rows/iter, 8 iters
    const int bx = tid & 7, by = tid >> 3;
    const __nv_bfloat16* gBw = g_Bw + (size_t)by * D_IN + bx * 8;
    const __nv_bfloat16* gBp = g_Bp + (size_t)by * D_PROJ + bx * 8;
    const uint32_t cpBoff = (uint32_t)(by * 128) + (uint32_t)((bx * 16) ^ ((by & 7) << 4));

    float4 aR[8];
    // ---- phase 1 prologue: stage 0 ----
    #pragma unroll
    for (int i = 0; i < 8; i++) aR[i] = *(const float4*)(gA + (size_t)(16 * i) * D_IN);
    #pragma unroll
    for (int i = 0; i < 8; i++) cp16(sB + cpBoff + i * 32 * 128, gBw + (size_t)(32 * i) * D_IN);
    CP_COMMIT();
    #pragma unroll
    for (int i = 0; i < 8; i++) {
        __nv_bfloat162 l2 = __floats2bfloat162_rn(aR[i].x, aR[i].y);
        __nv_bfloat162 h2 = __floats2bfloat162_rn(aR[i].z, aR[i].w);
        *(uint2*)(smem + OFF_A + stsAoff + i * 16 * 128) =
            make_uint2(*(uint32_t*)&l2, *(uint32_t*)&h2);
    }
    CP_WAIT0();
    __syncthreads();

    // ---- phase 1 mainloop: 16 stages of K=64 ----
    for (int kt = 0; kt < D_IN / KT; kt++) {
        const int cur = kt & 1, nxt = cur ^ 1;
        const bool more = (kt + 1) < (D_IN / KT);
        if (more) {
            const int kb = (kt + 1) * KT;
            #pragma unroll
            for (int i = 0; i < 8; i++)
                aR[i] = *(const float4*)(gA + (size_t)(16 * i) * D_IN + kb);
            #pragma unroll
            for (int i = 0; i < 8; i++)
                cp16(sB + nxt * 32768 + cpBoff + i * 32 * 128,
                     gBw + (size_t)(32 * i) * D_IN + kb);
            CP_COMMIT();
        }
        mma_stage(sA + cur * 16384, sB + cur * 32768, lane, wm, wn, acc);
        if (more) {
            #pragma unroll
            for (int i = 0; i < 8; i++) {
                __nv_bfloat162 l2 = __floats2bfloat162_rn(aR[i].x, aR[i].y);
                __nv_bfloat162 h2 = __floats2bfloat162_rn(aR[i].z, aR[i].w);
                *(uint2*)(smem + OFF_A + nxt * 16384 + stsAoff + i * 16 * 128) =
                    make_uint2(*(uint32_t*)&l2, *(uint32_t*)&h2);
            }
            CP_WAIT0();
        }
        __syncthreads();
    }

    // Prefetch prototype stage 0 into B buf0 (free: last phase-1 stage read buf1).
    // Overlaps the gmem latency with the whole norm epilogue below.
    #pragma unroll
    for (int i = 0; i < 8; i++)
        cp16(sB + cpBoff + i * 32 * 128, gBp + (size_t)(32 * i) * D_PROJ);
    CP_COMMIT();

    // ---- norm epilogue: Y = acc - c, row norms, z -> smem Z panels (bf16) ----
    const int c0 = wn * 64 + 2 * (lane & 3);
    float s[4][2];
    #pragma unroll
    for (int mi = 0; mi < 4; mi++) { s[mi][0] = 0.f; s[mi][1] = 0.f; }
    #pragma unroll
    for (int mi = 0; mi < 4; mi++)
        #pragma unroll
        for (int ni = 0; ni < 8; ni++)
            #pragma unroll
            for (int j = 0; j < 4; j++) {
                float v = acc[mi][ni][j] - cs[c0 + ni * 8 + (j & 1)];
                acc[mi][ni][j] = v;
                s[mi][j >> 1] = fmaf(v, v, s[mi][j >> 1]);
            }
    #pragma unroll
    for (int mi = 0; mi < 4; mi++)
        #pragma unroll
        for (int h = 0; h < 2; h++) {
            s[mi][h] += __shfl_xor_sync(0xffffffffu, s[mi][h], 1);
            s[mi][h] += __shfl_xor_sync(0xffffffffu, s[mi][h], 2);
        }
    const int r0 = wm * 64 + (lane >> 2);
    if ((lane & 3) == 0) {
        #pragma unroll
        for (int mi = 0; mi < 4; mi++)
            #pragma unroll
            for (int h = 0; h < 2; h++)
                red[(r0 + mi * 16 + h * 8) * 4 + wn] = s[mi][h];
    }
    __syncthreads();
    // Z panel wn: rows 0..127 x 64 cols, swizzled 128B rows (k-bytes ^ (row&7)<<4)
    #pragma unroll
    for (int mi = 0; mi < 4; mi++)
        #pragma unroll
        for (int h = 0; h < 2; h++) {
            const int r = r0 + mi * 16 + h * 8;
            float t = red[r * 4 + 0] + red[r * 4 + 1] + red[r * 4 + 2] + red[r * 4 + 3];
            float inv = 1.f / fmaxf(sqrtf(t), 1e-12f);
            const uint32_t zrow = sZ + (uint32_t)(wn * 16384 + r * 128);
            const uint32_t xr = (uint32_t)((r & 7) << 4);
            #pragma unroll
            for (int ni = 0; ni < 8; ni++) {
                __nv_bfloat162 zz = __floats2bfloat162_rn(acc[mi][ni][2 * h] * inv,
                                                          acc[mi][ni][2 * h + 1] * inv);
                const uint32_t boff = (uint32_t)((lane & 3) * 4 + ni * 16) ^ xr;
                asm volatile("st.shared.b32 [%0], %1;" :: "r"(zrow + boff),
                             "r"(*(uint32_t*)&zz) : "memory");
            }
        }

    // reuse acc for phase 2
    #pragma unroll
    for (int a = 0; a < 4; a++)
        #pragma unroll
        for (int b = 0; b < 8; b++)
            #pragma unroll
            for (int c = 0; c < 4; c++) acc[a][b][c] = 0.f;

    CP_WAIT0();        // prototype stage 0 landed
    __syncthreads();   // all Z panels visible

    // ---- phase 2: S = Z @ P^T over 4 k-stages (A = smem Z panels) ----
    for (int s2 = 0; s2 < 4; s2++) {
        const int cur = s2 & 1, nxt = cur ^ 1;
        const bool more = s2 < 3;
        if (more) {
            #pragma unroll
            for (int i = 0; i < 8; i++)
                cp16(sB + nxt * 32768 + cpBoff + i * 32 * 128,
                     gBp + (size_t)(32 * i) * D_PROJ + (s2 + 1) * KT);
            CP_COMMIT();
        }
        mma_stage(sZ + s2 * 16384, sB + cur * 32768, lane, wm, wn, acc);
        if (more) CP_WAIT0();
        __syncthreads();
    }

    // ---- final epilogue: score = -sqrt(max(1 + p2 - 2 s, 0)) ----
    #pragma unroll
    for (int mi = 0; mi < 4; mi++)
        #pragma unroll
        for (int h = 0; h < 2; h++) {
            const size_t rowoff = (size_t)(m0 + r0 + mi * 16 + h * 8) * N_CLS;
            #pragma unroll
            for (int ni = 0; ni < 8; ni++) {
                const int cc = c0 + ni * 8;
                float2 v;
                v.x = -sqrtf(fmaxf(1.0f + p2s[cc]     - 2.f * acc[mi][ni][2 * h],     0.f));
                v.y = -sqrtf(fmaxf(1.0f + p2s[cc + 1] - 2.f * acc[mi][ni][2 * h + 1], 0.f));
                *(float2*)(out + rowoff + cc) = v;
            }
        }
}

// ---------------------------------------------------------------------------
// Host launcher (graph-capturable: kernel launches only)
// ---------------------------------------------------------------------------
extern "C" void kernel_launch(void* const* d_in, const int* in_sizes, int n_in,
                              void* d_out, int out_size) {
    const float* X     = (const float*)d_in[0];
    const float* mean  = (const float*)d_in[1];
    const float* proj  = (const float*)d_in[2];
    const float* proto = (const float*)d_in[3];
    float* out = (float*)d_out;

    cudaFuncSetAttribute(proto_fused, cudaFuncAttributeMaxDynamicSharedMemorySize, SMEMF);

    proto_prep<<<42, 256>>>(mean, proj, proto);
    proto_fused<<<N_ROWS / TM, 256, SMEMF>>>(X, out);
}